// round 11
// baseline (speedup 1.0000x reference)
#include <cuda_runtime.h>
#include <cstdint>

#define HID    1024
#define BATCH  32
#define LAYERS 3
#define OUTDIM 2500
#define GRID_N 50
#define MODES  32
#define TIME   64

#define GRU_MT  192         // 3072/16 m-tiles per matrix
#define GRU_KT  128         // 1024/8 k8-tiles
#define KS8     8           // K-slices per matrix (K=128 each)
#define FC_MT   160         // padded 2560/16
#define FC_KT   128
#define KS_FC   16
#define KSLICE_FC 64
#define M_FC_PAD 2512

// ---------------- persistent device state ------------------------------------
__device__ float g_h[2][LAYERS][BATCH][HID];
__device__ float g_x[BATCH][HID];
__device__ float g_ct[MODES][GRID_N];
__device__ float g_st[MODES][GRID_N];
__device__ float g_part6[6 * KS8 * 3072 * 32];        // GRU split-K partials
__device__ float g_fpart[KS_FC * 32 * M_FC_PAD];      // FC partials
__device__ int   g_ctr[LAYERS][16];                   // cell-epilogue counters

// fragment-swizzled fp32 weights: [mat][mt][kt8][128]; mats 0-2 ih, 3-5 hh
__device__ float g_Wsw[(size_t)6 * GRU_MT * GRU_KT * 128];   // 75.5 MB
__device__ float g_Fsw[(size_t)FC_MT * FC_KT * 128];         // 10.5 MB

// ---------------- helpers ----------------------------------------------------
__device__ __forceinline__ uint32_t f2tf(float f) {
    uint32_t u;
    asm("cvt.rna.tf32.f32 %0, %1;" : "=r"(u) : "f"(f));
    return u;
}

__device__ __forceinline__ void mma1688(float* c,
                                        uint32_t a0, uint32_t a1, uint32_t a2, uint32_t a3,
                                        uint32_t b0, uint32_t b1) {
    asm volatile(
        "mma.sync.aligned.m16n8k8.row.col.f32.tf32.tf32.f32 "
        "{%0,%1,%2,%3}, {%4,%5,%6,%7}, {%8,%9}, {%0,%1,%2,%3};"
        : "+f"(c[0]), "+f"(c[1]), "+f"(c[2]), "+f"(c[3])
        : "r"(a0), "r"(a1), "r"(a2), "r"(a3), "r"(b0), "r"(b1));
}

__device__ __forceinline__ uint32_t smem_u32(const void* p) {
    return (uint32_t)__cvta_generic_to_shared(p);
}

__device__ __forceinline__ void cp16(uint32_t dst, const void* src) {
    asm volatile("cp.async.cg.shared.global [%0], [%1], 16;" :: "r"(dst), "l"(src));
}
__device__ __forceinline__ void cp_commit() {
    asm volatile("cp.async.commit_group;");
}
template<int N> __device__ __forceinline__ void cp_wait() {
    asm volatile("cp.async.wait_group %0;" :: "n"(N));
}

// ---------------- init -------------------------------------------------------
__global__ void init_kernel(const float* __restrict__ x)
{
    int tid    = blockIdx.x * blockDim.x + threadIdx.x;
    int stride = gridDim.x * blockDim.x;

    float* hflat = (float*)g_h;
    for (int i = tid; i < 2 * LAYERS * BATCH * HID; i += stride) hflat[i] = 0.0f;

    float* xflat = (float*)g_x;
    for (int i = tid; i < BATCH * HID; i += stride) xflat[i] = x[i];

    if (tid < LAYERS * 16) ((int*)g_ctr)[tid] = 0;

    for (int i = tid; i < MODES * GRID_N; i += stride) {
        int t = i / GRID_N;
        int n = i % GRID_N;
        float arg = 2.0f * (float)(t - 16) * (float)n / 50.0f;  // units of pi
        g_ct[t][n] = cospif(arg);
        g_st[t][n] = sinpif(arg);
    }
}

// ---------------- weight repack: fp32 fragment order -------------------------
__global__ void repack_gru(const float* __restrict__ W_ih,
                           const float* __restrict__ W_hh)
{
    int64_t total = (int64_t)6 * GRU_MT * GRU_KT * 128;
    for (int64_t idx = (int64_t)blockIdx.x * blockDim.x + threadIdx.x;
         idx < total; idx += (int64_t)gridDim.x * blockDim.x) {
        int within = (int)(idx & 127);
        int e    = within & 3;
        int lane = within >> 2;
        int kt   = (int)((idx >> 7) & (GRU_KT - 1));
        int tmp  = (int)(idx >> 14);           // mat*GRU_MT + mt
        int mt   = tmp % GRU_MT;
        int mat  = tmp / GRU_MT;
        int l    = mat % 3;
        const float* src = ((mat < 3) ? W_ih : W_hh) + (size_t)l * 3 * HID * HID;
        int g = lane >> 2, t = lane & 3;
        int r = mt * 16 + g + (e & 1) * 8;
        int c = kt * 8 + t + (e >> 1) * 4;
        g_Wsw[idx] = src[(size_t)r * HID + c];
    }
}

__global__ void repack_fc(const float* __restrict__ fc_w)
{
    int64_t total = (int64_t)FC_MT * FC_KT * 128;
    for (int64_t idx = (int64_t)blockIdx.x * blockDim.x + threadIdx.x;
         idx < total; idx += (int64_t)gridDim.x * blockDim.x) {
        int within = (int)(idx & 127);
        int e    = within & 3;
        int lane = within >> 2;
        int kt   = (int)((idx >> 7) & (FC_KT - 1));
        int mt   = (int)(idx >> 14);
        int g = lane >> 2, t = lane & 3;
        int r = mt * 16 + g + (e & 1) * 8;
        int c = kt * 8 + t + (e >> 1) * 4;
        g_Fsw[idx] = (r < OUTDIM) ? fc_w[(size_t)r * HID + c] : 0.0f;
    }
}

// ---------------- GRU gate GEMM + fused cell epilogue ------------------------
// grid (48, 8, njobs). After partial stores, CTAs of jobs z < narrive arrive on
// a per-unit-group counter; the LAST CTA of each group reduces partials and
// runs the GRU cell for its 64 units (deterministic: fixed read order).
__global__ __launch_bounds__(128) void gru_gemm(
    int src, int j0, int j1, int j2, int j3,
    int cell_layer, int ctr_target, int narrive,
    const float* __restrict__ b_ih_all, const float* __restrict__ b_hh_all)
{
    __shared__ float4 sA[2 * 4 * 4 * 32];   // [slot][warp][kt][lane]
    __shared__ float  vB[32 * 132];         // raw fp32 B
    __shared__ int    s_last;

    const int mat  = (blockIdx.z == 0) ? j0 : (blockIdx.z == 1) ? j1
                   : (blockIdx.z == 2) ? j2 : j3;
    const int ks   = blockIdx.y;
    const int warp = threadIdx.x >> 5;
    const int lane = threadIdx.x & 31;
    const int g    = lane >> 2;
    const int t    = lane & 3;
    const int m0   = blockIdx.x * 64 + warp * 16;
    const int koff = ks * 128;
    const int l    = mat % 3;
    const int dst  = src ^ 1;

    const int mt = blockIdx.x * 4 + warp;
    const float4* pA4 = (const float4*)(g_Wsw
                      + (((size_t)mat * GRU_MT + mt) * GRU_KT + ks * 16) * 128);
    const uint32_t sA_base = smem_u32(sA);
    const uint32_t vB_base = smem_u32(vB);

    // group 0: B (raw fp32, 16 KB)
    const float* bsrc = (mat >= 3) ? &g_h[src][l][0][0]
                      : (l == 0)   ? &g_x[0][0]
                                   : &g_h[dst][l - 1][0][0];
    {
        int n = threadIdx.x >> 2;
        int q = threadIdx.x & 3;
        const float* srcp = bsrc + n * HID + koff + q * 32;
        uint32_t dstp = vB_base + (n * 132 + q * 32) * 4;
        #pragma unroll
        for (int j = 0; j < 8; j++)
            cp16(dstp + j * 16, srcp + j * 4);
        cp_commit();
    }

    // groups 1,2: A chunks 0,1
    #pragma unroll
    for (int c = 0; c < 2; c++) {
        #pragma unroll
        for (int kt = 0; kt < 4; kt++) {
            uint32_t d = sA_base + ((((c * 4 + warp) * 4 + kt) * 32 + lane) << 4);
            cp16(d, pA4 + (c * 4 + kt) * 32 + lane);
        }
        cp_commit();
    }

    cp_wait<2>();
    __syncthreads();

    float c4[4][4] = {};

    auto process = [&](int c, int slot) {
        #pragma unroll
        for (int kt = 0; kt < 4; kt++) {
            float4 fr = sA[((slot * 4 + warp) * 4 + kt) * 32 + lane];
            int k0 = (c * 4 + kt) * 8;
            uint32_t ah0 = f2tf(fr.x), ah1 = f2tf(fr.y), ah2 = f2tf(fr.z), ah3 = f2tf(fr.w);
            uint32_t al0 = f2tf(fr.x - __uint_as_float(ah0));
            uint32_t al1 = f2tf(fr.y - __uint_as_float(ah1));
            uint32_t al2 = f2tf(fr.z - __uint_as_float(ah2));
            uint32_t al3 = f2tf(fr.w - __uint_as_float(ah3));
            #pragma unroll
            for (int nt = 0; nt < 4; nt++) {
                int n = nt * 8 + g;
                float b0 = vB[n * 132 + k0 + t];
                float b1 = vB[n * 132 + k0 + t + 4];
                uint32_t bh0 = f2tf(b0);
                uint32_t bh1 = f2tf(b1);
                uint32_t bl0 = f2tf(b0 - __uint_as_float(bh0));
                uint32_t bl1 = f2tf(b1 - __uint_as_float(bh1));
                mma1688(c4[nt], ah0, ah1, ah2, ah3, bh0, bh1);
                mma1688(c4[nt], ah0, ah1, ah2, ah3, bl0, bl1);
                mma1688(c4[nt], al0, al1, al2, al3, bh0, bh1);
            }
        }
    };

    auto issue_chunk = [&](int c, int slot) {
        #pragma unroll
        for (int kt = 0; kt < 4; kt++) {
            uint32_t d = sA_base + ((((slot * 4 + warp) * 4 + kt) * 32 + lane) << 4);
            cp16(d, pA4 + (c * 4 + kt) * 32 + lane);
        }
        cp_commit();
    };

    cp_wait<1>();
    process(0, 0);
    issue_chunk(2, 0);
    cp_wait<1>();
    process(1, 1);
    issue_chunk(3, 1);
    cp_wait<1>();
    process(2, 0);
    cp_wait<0>();
    process(3, 1);

    #pragma unroll
    for (int nt = 0; nt < 4; nt++) {
        int n = nt * 8 + 2 * t;
        float* base = g_part6 + (((size_t)mat * KS8 + ks) * 3072 + (m0 + g)) * 32 + n;
        *(float2*)base            = make_float2(c4[nt][0], c4[nt][1]);
        *(float2*)(base + 8 * 32) = make_float2(c4[nt][2], c4[nt][3]);
    }

    // ---- fused cell epilogue (last CTA per unit-group) ----
    if (blockIdx.z < narrive) {
        __threadfence();
        __syncthreads();
        const int grp = blockIdx.x & 15;
        if (threadIdx.x == 0) {
            int old = atomicAdd(&g_ctr[cell_layer][grp], 1);
            s_last = (old == ctr_target - 1);
        }
        __syncthreads();
        if (s_last) {
            __threadfence();
            const int u0 = grp * 64;
            const float* bih = b_ih_all + cell_layer * 3 * HID;
            const float* bhh = b_hh_all + cell_layer * 3 * HID;
            const float* pih = g_part6 + (size_t)cell_layer * KS8 * 3072 * 32;
            const float* phh = g_part6 + (size_t)(3 + cell_layer) * KS8 * 3072 * 32;

            for (int idx = threadIdx.x; idx < 64 * 32; idx += 128) {
                int b = idx & 31;
                int u = u0 + (idx >> 5);
                float i_r = 0.f, i_z = 0.f, i_n = 0.f;
                float h_r = 0.f, h_z = 0.f, h_n = 0.f;
                #pragma unroll
                for (int s = 0; s < KS8; s++) {
                    const float* p = pih + (size_t)s * 3072 * 32;
                    i_r += p[(u)        * 32 + b];
                    i_z += p[(u + 1024) * 32 + b];
                    i_n += p[(u + 2048) * 32 + b];
                }
                #pragma unroll
                for (int s = 0; s < KS8; s++) {
                    const float* p = phh + (size_t)s * 3072 * 32;
                    h_r += p[(u)        * 32 + b];
                    h_z += p[(u + 1024) * 32 + b];
                    h_n += p[(u + 2048) * 32 + b];
                }
                i_r += bih[u];           h_r += bhh[u];
                i_z += bih[u + HID];     h_z += bhh[u + HID];
                i_n += bih[u + 2 * HID]; h_n += bhh[u + 2 * HID];

                float r = 1.0f / (1.0f + expf(-(i_r + h_r)));
                float z = 1.0f / (1.0f + expf(-(i_z + h_z)));
                float nn = tanhf(i_n + r * h_n);

                float h_old = g_h[src][cell_layer][b][u];
                g_h[dst][cell_layer][b][u] = (1.0f - z) * nn + z * h_old;
            }
            __syncthreads();
            if (threadIdx.x == 0) g_ctr[cell_layer][grp] = 0;
        }
    }
}

// ---------------- FC GEMM (split-K, 3xTF32, cp.async, raw-B) -----------------
__global__ __launch_bounds__(128) void fc_gemm(int src)
{
    __shared__ float4 sA[2 * 4 * 4 * 32];   // 16 KB, 2 ring slots
    __shared__ float  vB[32 * 76];

    const int dst  = src ^ 1;
    const int ks   = blockIdx.y;
    const int warp = threadIdx.x >> 5;
    const int lane = threadIdx.x & 31;
    const int g    = lane >> 2;
    const int t    = lane & 3;
    const int m0   = blockIdx.x * 64 + warp * 16;
    const int koff = ks * KSLICE_FC;

    const int mt = blockIdx.x * 4 + warp;
    const float4* pA4 = (const float4*)(g_Fsw
                      + (((size_t)mt) * FC_KT + ks * 8) * 128);
    const uint32_t sA_base = smem_u32(sA);
    const uint32_t vB_base = smem_u32(vB);

    const float* bsrc = &g_h[dst][LAYERS - 1][0][0];
    {
        int n = threadIdx.x >> 2;
        int q = threadIdx.x & 3;
        const float* srcp = bsrc + n * HID + koff + q * 16;
        uint32_t dstp = vB_base + (n * 76 + q * 16) * 4;
        #pragma unroll
        for (int j = 0; j < 4; j++)
            cp16(dstp + j * 16, srcp + j * 4);
        cp_commit();
    }

    #pragma unroll
    for (int c = 0; c < 2; c++) {
        #pragma unroll
        for (int kt = 0; kt < 4; kt++) {
            uint32_t d = sA_base + ((((c * 4 + warp) * 4 + kt) * 32 + lane) << 4);
            cp16(d, pA4 + (c * 4 + kt) * 32 + lane);
        }
        cp_commit();
    }

    cp_wait<2>();
    __syncthreads();

    float c4[4][4] = {};

    auto process = [&](int c, int slot) {
        #pragma unroll
        for (int kt = 0; kt < 4; kt++) {
            float4 fr = sA[((slot * 4 + warp) * 4 + kt) * 32 + lane];
            int k0 = (c * 4 + kt) * 8;
            uint32_t ah0 = f2tf(fr.x), ah1 = f2tf(fr.y), ah2 = f2tf(fr.z), ah3 = f2tf(fr.w);
            uint32_t al0 = f2tf(fr.x - __uint_as_float(ah0));
            uint32_t al1 = f2tf(fr.y - __uint_as_float(ah1));
            uint32_t al2 = f2tf(fr.z - __uint_as_float(ah2));
            uint32_t al3 = f2tf(fr.w - __uint_as_float(ah3));
            #pragma unroll
            for (int nt = 0; nt < 4; nt++) {
                int n = nt * 8 + g;
                float b0 = vB[n * 76 + k0 + t];
                float b1 = vB[n * 76 + k0 + t + 4];
                uint32_t bh0 = f2tf(b0);
                uint32_t bh1 = f2tf(b1);
                uint32_t bl0 = f2tf(b0 - __uint_as_float(bh0));
                uint32_t bl1 = f2tf(b1 - __uint_as_float(bh1));
                mma1688(c4[nt], ah0, ah1, ah2, ah3, bh0, bh1);
                mma1688(c4[nt], ah0, ah1, ah2, ah3, bl0, bl1);
                mma1688(c4[nt], al0, al1, al2, al3, bh0, bh1);
            }
        }
    };

    cp_wait<1>();
    process(0, 0);
    cp_wait<0>();
    process(1, 1);

    #pragma unroll
    for (int nt = 0; nt < 4; nt++) {
        #pragma unroll
        for (int j = 0; j < 4; j++) {
            int n = nt * 8 + 2 * t + (j & 1);
            int m = m0 + g + ((j >> 1) * 8);
            if (m < OUTDIM)
                g_fpart[((size_t)ks * 32 + n) * M_FC_PAD + m] = c4[nt][j];
        }
    }
}

// ---------------- spectral crop: FC reduce+bias, DFT, feedback ---------------
__global__ __launch_bounds__(512) void spectral_kernel(
    const float* __restrict__ fc_b, float* __restrict__ outp)
{
    const int b = blockIdx.x;
    __shared__ float a[OUTDIM];
    __shared__ float cre[GRID_N * MODES];
    __shared__ float cim[GRID_N * MODES];

    for (int i = threadIdx.x; i < OUTDIM; i += blockDim.x) {
        float s = fc_b[i];
        #pragma unroll
        for (int ks = 0; ks < KS_FC; ks++)
            s += g_fpart[((size_t)ks * 32 + b) * M_FC_PAD + i];
        a[i] = s;
        outp[b * OUTDIM + i] = s;
    }
    __syncthreads();

    for (int i = threadIdx.x; i < GRID_N * MODES; i += blockDim.x) {
        int m = i / MODES;
        int q = i % MODES;
        float sre = 0.f, sim = 0.f;
        #pragma unroll 5
        for (int n = 0; n < GRID_N; n++) {
            float v = a[m * GRID_N + n];
            sre += v * g_ct[q][n];
            sim -= v * g_st[q][n];
        }
        cre[m * MODES + q] = sre;
        cim[m * MODES + q] = sim;
    }
    __syncthreads();

    for (int i = threadIdx.x; i < MODES * MODES; i += blockDim.x) {
        int p = i / MODES;
        int q = i % MODES;
        float s = 0.f;
        #pragma unroll 5
        for (int m = 0; m < GRID_N; m++)
            s += g_ct[p][m] * cre[m * MODES + q] + g_st[p][m] * cim[m * MODES + q];
        g_x[b][i] = s;
    }
}

// ---------------- driver -----------------------------------------------------
extern "C" void kernel_launch(void* const* d_in, const int* in_sizes, int n_in,
                              void* d_out, int out_size)
{
    const float* x     = (const float*)d_in[0];
    const float* W_ih  = (const float*)d_in[1];
    const float* W_hh  = (const float*)d_in[2];
    const float* b_ih  = (const float*)d_in[3];
    const float* b_hh  = (const float*)d_in[4];
    const float* fc_w  = (const float*)d_in[5];
    const float* fc_b  = (const float*)d_in[6];
    float*       out   = (float*)d_out;

    init_kernel<<<64, 256>>>(x);
    repack_gru<<<592, 256>>>(W_ih, W_hh);
    repack_fc<<<128, 256>>>(fc_w);

    for (int t = 0; t < TIME; t++) {
        int src = t & 1;
        float* outp = out + (size_t)t * BATCH * OUTDIM;

        // K1: ih0 + hh0..2 (+ fused cell0; ih0/hh0 jobs arrive, target 48)
        gru_gemm<<<dim3(48, 8, 4), 128>>>(src, 0, 3, 4, 5, 0, 48, 2, b_ih, b_hh);
        // G2: ih1 (+ fused cell1; hh1 partials from K1, target 24)
        gru_gemm<<<dim3(48, 8, 1), 128>>>(src, 1, 0, 0, 0, 1, 24, 1, b_ih, b_hh);
        // G3: ih2 (+ fused cell2)
        gru_gemm<<<dim3(48, 8, 1), 128>>>(src, 2, 0, 0, 0, 2, 24, 1, b_ih, b_hh);
        fc_gemm<<<dim3(40, KS_FC), 128>>>(src);
        spectral_kernel<<<BATCH, 512>>>(fc_b, outp);
    }
}

// round 12
// speedup vs baseline: 1.5317x; 1.5317x over previous
#include <cuda_runtime.h>
#include <cstdint>

#define HID    1024
#define BATCH  32
#define LAYERS 3
#define OUTDIM 2500
#define GRID_N 50
#define MODES  32
#define TIME   64

#define GRU_MT  192         // 3072/16 m-tiles per matrix
#define GRU_KT  128         // 1024/8 k8-tiles
#define KS8     8           // K-slices per matrix (K=128 each)
#define FC_MT   160         // padded 2560/16
#define FC_KT   128
#define KS_FC   16
#define KSLICE_FC 64
#define M_FC_PAD 2512

// ---------------- persistent device state ------------------------------------
__device__ float g_h[2][LAYERS][BATCH][HID];
__device__ float g_x[BATCH][HID];
__device__ float g_ct[MODES][GRID_N];
__device__ float g_st[MODES][GRID_N];
__device__ float g_part6[6 * KS8 * 3072 * 32];        // GRU split-K partials
__device__ float g_fpart[KS_FC * 32 * M_FC_PAD];      // FC partials

// fragment-swizzled fp32 weights: [mat][mt][kt8][128]; mats 0-2 ih, 3-5 hh
__device__ float g_Wsw[(size_t)6 * GRU_MT * GRU_KT * 128];   // 75.5 MB
__device__ float g_Fsw[(size_t)FC_MT * FC_KT * 128];         // 10.5 MB

// ---------------- helpers ----------------------------------------------------
__device__ __forceinline__ uint32_t f2tf(float f) {
    uint32_t u;
    asm("cvt.rna.tf32.f32 %0, %1;" : "=r"(u) : "f"(f));
    return u;
}

__device__ __forceinline__ void mma1688(float* c,
                                        uint32_t a0, uint32_t a1, uint32_t a2, uint32_t a3,
                                        uint32_t b0, uint32_t b1) {
    asm volatile(
        "mma.sync.aligned.m16n8k8.row.col.f32.tf32.tf32.f32 "
        "{%0,%1,%2,%3}, {%4,%5,%6,%7}, {%8,%9}, {%0,%1,%2,%3};"
        : "+f"(c[0]), "+f"(c[1]), "+f"(c[2]), "+f"(c[3])
        : "r"(a0), "r"(a1), "r"(a2), "r"(a3), "r"(b0), "r"(b1));
}

__device__ __forceinline__ uint32_t smem_u32(const void* p) {
    return (uint32_t)__cvta_generic_to_shared(p);
}

__device__ __forceinline__ void cp16(uint32_t dst, const void* src) {
    asm volatile("cp.async.cg.shared.global [%0], [%1], 16;" :: "r"(dst), "l"(src));
}
__device__ __forceinline__ void cp_commit() {
    asm volatile("cp.async.commit_group;");
}
template<int N> __device__ __forceinline__ void cp_wait() {
    asm volatile("cp.async.wait_group %0;" :: "n"(N));
}

// ---------------- init -------------------------------------------------------
__global__ void init_kernel(const float* __restrict__ x)
{
    int tid    = blockIdx.x * blockDim.x + threadIdx.x;
    int stride = gridDim.x * blockDim.x;

    float* hflat = (float*)g_h;
    for (int i = tid; i < 2 * LAYERS * BATCH * HID; i += stride) hflat[i] = 0.0f;

    float* xflat = (float*)g_x;
    for (int i = tid; i < BATCH * HID; i += stride) xflat[i] = x[i];

    for (int i = tid; i < MODES * GRID_N; i += stride) {
        int t = i / GRID_N;
        int n = i % GRID_N;
        float arg = 2.0f * (float)(t - 16) * (float)n / 50.0f;  // units of pi
        g_ct[t][n] = cospif(arg);
        g_st[t][n] = sinpif(arg);
    }
}

// ---------------- weight repack: fp32 fragment order -------------------------
// layout: [mat][mt][kt8][lane*4+e]; 128 floats (7 bits) per 16x8 tile.
// e0=(g,t) e1=(g+8,t) e2=(g,t+4) e3=(g+8,t+4)
__global__ void repack_gru(const float* __restrict__ W_ih,
                           const float* __restrict__ W_hh)
{
    int64_t total = (int64_t)6 * GRU_MT * GRU_KT * 128;
    for (int64_t idx = (int64_t)blockIdx.x * blockDim.x + threadIdx.x;
         idx < total; idx += (int64_t)gridDim.x * blockDim.x) {
        int within = (int)(idx & 127);
        int e    = within & 3;
        int lane = within >> 2;
        int kt   = (int)((idx >> 7) & (GRU_KT - 1));
        int tmp  = (int)(idx >> 14);           // mat*GRU_MT + mt
        int mt   = tmp % GRU_MT;
        int mat  = tmp / GRU_MT;
        int l    = mat % 3;
        const float* src = ((mat < 3) ? W_ih : W_hh) + (size_t)l * 3 * HID * HID;
        int g = lane >> 2, t = lane & 3;
        int r = mt * 16 + g + (e & 1) * 8;
        int c = kt * 8 + t + (e >> 1) * 4;
        g_Wsw[idx] = src[(size_t)r * HID + c];
    }
}

__global__ void repack_fc(const float* __restrict__ fc_w)
{
    int64_t total = (int64_t)FC_MT * FC_KT * 128;
    for (int64_t idx = (int64_t)blockIdx.x * blockDim.x + threadIdx.x;
         idx < total; idx += (int64_t)gridDim.x * blockDim.x) {
        int within = (int)(idx & 127);
        int e    = within & 3;
        int lane = within >> 2;
        int kt   = (int)((idx >> 7) & (FC_KT - 1));
        int mt   = (int)(idx >> 14);
        int g = lane >> 2, t = lane & 3;
        int r = mt * 16 + g + (e & 1) * 8;
        int c = kt * 8 + t + (e >> 1) * 4;
        g_Fsw[idx] = (r < OUTDIM) ? fc_w[(size_t)r * HID + c] : 0.0f;
    }
}

// ---------------- GRU gate GEMM (split-K, 3xTF32, cp.async, raw-B) -----------
// grid (48, 8, njobs): x = m-block (64 rows), y = K-slice (K=128), z = job.
// smem: A ring 2 slots x 4KB + raw fp32 B (16.9KB) = 24.5KB -> 8 CTAs/SM.
__global__ __launch_bounds__(128, 8) void gru_gemm(
    int src, int j0, int j1, int j2, int j3)
{
    __shared__ float4 sA[2 * 4 * 2 * 32];   // [slot][warp][kt2][lane], 8 KB
    __shared__ float  vB[32 * 132];         // raw fp32 B, stride 132

    const int mat  = (blockIdx.z == 0) ? j0 : (blockIdx.z == 1) ? j1
                   : (blockIdx.z == 2) ? j2 : j3;
    const int ks   = blockIdx.y;
    const int warp = threadIdx.x >> 5;
    const int lane = threadIdx.x & 31;
    const int g    = lane >> 2;
    const int t    = lane & 3;
    const int m0   = blockIdx.x * 64 + warp * 16;
    const int koff = ks * 128;
    const int l    = mat % 3;

    const int mt = blockIdx.x * 4 + warp;
    const float4* pA4 = (const float4*)(g_Wsw
                      + (((size_t)mat * GRU_MT + mt) * GRU_KT + ks * 16) * 128);
    const uint32_t sA_base = smem_u32(sA);
    const uint32_t vB_base = smem_u32(vB);

    // group 0: B (raw fp32, 16 KB), each thread copies 128 B of one row-quarter
    const float* bsrc = (mat >= 3) ? &g_h[src][l][0][0]
                      : (l == 0)   ? &g_x[0][0]
                                   : &g_h[src ^ 1][l - 1][0][0];
    {
        int n = threadIdx.x >> 2;
        int q = threadIdx.x & 3;
        const float* srcp = bsrc + n * HID + koff + q * 32;
        uint32_t dstp = vB_base + (n * 132 + q * 32) * 4;
        #pragma unroll
        for (int j = 0; j < 8; j++)
            cp16(dstp + j * 16, srcp + j * 4);
        cp_commit();
    }

    auto issue_chunk = [&](int c, int slot) {
        #pragma unroll
        for (int kt = 0; kt < 2; kt++) {
            uint32_t d = sA_base + ((((slot * 4 + warp) * 2 + kt) * 32 + lane) << 4);
            cp16(d, pA4 + (c * 2 + kt) * 32 + lane);
        }
        cp_commit();
    };

    // groups 1,2: A chunks 0,1 (each chunk = 2 k8-tiles = 4 KB)
    issue_chunk(0, 0);
    issue_chunk(1, 1);

    cp_wait<2>();            // B complete
    __syncthreads();

    float c4[4][4] = {};

    auto process = [&](int c, int slot) {
        #pragma unroll
        for (int kt = 0; kt < 2; kt++) {
            float4 fr = sA[((slot * 4 + warp) * 2 + kt) * 32 + lane];
            int k0 = (c * 2 + kt) * 8;
            uint32_t ah0 = f2tf(fr.x), ah1 = f2tf(fr.y), ah2 = f2tf(fr.z), ah3 = f2tf(fr.w);
            uint32_t al0 = f2tf(fr.x - __uint_as_float(ah0));
            uint32_t al1 = f2tf(fr.y - __uint_as_float(ah1));
            uint32_t al2 = f2tf(fr.z - __uint_as_float(ah2));
            uint32_t al3 = f2tf(fr.w - __uint_as_float(ah3));
            #pragma unroll
            for (int nt = 0; nt < 4; nt++) {
                int n = nt * 8 + g;
                float b0 = vB[n * 132 + k0 + t];
                float b1 = vB[n * 132 + k0 + t + 4];
                uint32_t bh0 = f2tf(b0);
                uint32_t bh1 = f2tf(b1);
                uint32_t bl0 = f2tf(b0 - __uint_as_float(bh0));
                uint32_t bl1 = f2tf(b1 - __uint_as_float(bh1));
                mma1688(c4[nt], ah0, ah1, ah2, ah3, bh0, bh1);
                mma1688(c4[nt], ah0, ah1, ah2, ah3, bl0, bl1);
                mma1688(c4[nt], al0, al1, al2, al3, bh0, bh1);
            }
        }
    };

    // 8 chunks through 2 slots
    cp_wait<1>();  process(0, 0);  issue_chunk(2, 0);
    cp_wait<1>();  process(1, 1);  issue_chunk(3, 1);
    cp_wait<1>();  process(2, 0);  issue_chunk(4, 0);
    cp_wait<1>();  process(3, 1);  issue_chunk(5, 1);
    cp_wait<1>();  process(4, 0);  issue_chunk(6, 0);
    cp_wait<1>();  process(5, 1);  issue_chunk(7, 1);
    cp_wait<1>();  process(6, 0);
    cp_wait<0>();  process(7, 1);

    #pragma unroll
    for (int nt = 0; nt < 4; nt++) {
        int n = nt * 8 + 2 * t;
        float* base = g_part6 + (((size_t)mat * KS8 + ks) * 3072 + (m0 + g)) * 32 + n;
        *(float2*)base            = make_float2(c4[nt][0], c4[nt][1]);
        *(float2*)(base + 8 * 32) = make_float2(c4[nt][2], c4[nt][3]);
    }
}

// ---------------- GRU cell pointwise -----------------------------------------
__global__ __launch_bounds__(256) void gru_cell(
    int layer, int src,
    const float* __restrict__ b_ih_all,
    const float* __restrict__ b_hh_all)
{
    const int dst = src ^ 1;
    const int gid = blockIdx.x * 256 + threadIdx.x;
    const int b   = gid & 31;
    const int u   = gid >> 5;

    float i_r = 0.f, i_z = 0.f, i_n = 0.f, h_r = 0.f, h_z = 0.f, h_n = 0.f;
    #pragma unroll
    for (int ks = 0; ks < KS8; ks++) {
        const float* p = g_part6 + ((size_t)layer * KS8 + ks) * 3072 * 32;
        i_r += p[(u)        * 32 + b];
        i_z += p[(u + 1024) * 32 + b];
        i_n += p[(u + 2048) * 32 + b];
    }
    #pragma unroll
    for (int ks = 0; ks < KS8; ks++) {
        const float* p = g_part6 + ((size_t)(3 + layer) * KS8 + ks) * 3072 * 32;
        h_r += p[(u)        * 32 + b];
        h_z += p[(u + 1024) * 32 + b];
        h_n += p[(u + 2048) * 32 + b];
    }

    const float* bih = b_ih_all + layer * 3 * HID;
    const float* bhh = b_hh_all + layer * 3 * HID;
    i_r += bih[u];           h_r += bhh[u];
    i_z += bih[u + HID];     h_z += bhh[u + HID];
    i_n += bih[u + 2 * HID]; h_n += bhh[u + 2 * HID];

    float r = 1.0f / (1.0f + expf(-(i_r + h_r)));
    float z = 1.0f / (1.0f + expf(-(i_z + h_z)));
    float n = tanhf(i_n + r * h_n);

    float h_old = g_h[src][layer][b][u];
    g_h[dst][layer][b][u] = (1.0f - z) * n + z * h_old;
}

// ---------------- FC GEMM (split-K, 3xTF32, cp.async, raw-B) -----------------
// grid (40, 16). Partials -> g_fpart[(ks*32+n)*M_FC_PAD + m].
__global__ __launch_bounds__(128, 8) void fc_gemm(int src)
{
    __shared__ float4 sA[2 * 4 * 2 * 32];   // 8 KB, 2 ring slots of 2 k8-tiles
    __shared__ float  vB[32 * 76];

    const int dst  = src ^ 1;
    const int ks   = blockIdx.y;
    const int warp = threadIdx.x >> 5;
    const int lane = threadIdx.x & 31;
    const int g    = lane >> 2;
    const int t    = lane & 3;
    const int m0   = blockIdx.x * 64 + warp * 16;
    const int koff = ks * KSLICE_FC;

    const int mt = blockIdx.x * 4 + warp;
    const float4* pA4 = (const float4*)(g_Fsw
                      + (((size_t)mt) * FC_KT + ks * 8) * 128);
    const uint32_t sA_base = smem_u32(sA);
    const uint32_t vB_base = smem_u32(vB);

    // group 0: B raw fp32 (8 KB)
    const float* bsrc = &g_h[dst][LAYERS - 1][0][0];
    {
        int n = threadIdx.x >> 2;
        int q = threadIdx.x & 3;
        const float* srcp = bsrc + n * HID + koff + q * 16;
        uint32_t dstp = vB_base + (n * 76 + q * 16) * 4;
        #pragma unroll
        for (int j = 0; j < 4; j++)
            cp16(dstp + j * 16, srcp + j * 4);
        cp_commit();
    }

    auto issue_chunk = [&](int c, int slot) {
        #pragma unroll
        for (int kt = 0; kt < 2; kt++) {
            uint32_t d = sA_base + ((((slot * 4 + warp) * 2 + kt) * 32 + lane) << 4);
            cp16(d, pA4 + (c * 2 + kt) * 32 + lane);
        }
        cp_commit();
    };

    issue_chunk(0, 0);
    issue_chunk(1, 1);

    cp_wait<2>();
    __syncthreads();

    float c4[4][4] = {};

    auto process = [&](int c, int slot) {
        #pragma unroll
        for (int kt = 0; kt < 2; kt++) {
            float4 fr = sA[((slot * 4 + warp) * 2 + kt) * 32 + lane];
            int k0 = (c * 2 + kt) * 8;
            uint32_t ah0 = f2tf(fr.x), ah1 = f2tf(fr.y), ah2 = f2tf(fr.z), ah3 = f2tf(fr.w);
            uint32_t al0 = f2tf(fr.x - __uint_as_float(ah0));
            uint32_t al1 = f2tf(fr.y - __uint_as_float(ah1));
            uint32_t al2 = f2tf(fr.z - __uint_as_float(ah2));
            uint32_t al3 = f2tf(fr.w - __uint_as_float(ah3));
            #pragma unroll
            for (int nt = 0; nt < 4; nt++) {
                int n = nt * 8 + g;
                float b0 = vB[n * 76 + k0 + t];
                float b1 = vB[n * 76 + k0 + t + 4];
                uint32_t bh0 = f2tf(b0);
                uint32_t bh1 = f2tf(b1);
                uint32_t bl0 = f2tf(b0 - __uint_as_float(bh0));
                uint32_t bl1 = f2tf(b1 - __uint_as_float(bh1));
                mma1688(c4[nt], ah0, ah1, ah2, ah3, bh0, bh1);
                mma1688(c4[nt], ah0, ah1, ah2, ah3, bl0, bl1);
                mma1688(c4[nt], al0, al1, al2, al3, bh0, bh1);
            }
        }
    };

    // 4 chunks through 2 slots
    cp_wait<1>();  process(0, 0);  issue_chunk(2, 0);
    cp_wait<1>();  process(1, 1);  issue_chunk(3, 1);
    cp_wait<1>();  process(2, 0);
    cp_wait<0>();  process(3, 1);

    #pragma unroll
    for (int nt = 0; nt < 4; nt++) {
        #pragma unroll
        for (int j = 0; j < 4; j++) {
            int n = nt * 8 + 2 * t + (j & 1);
            int m = m0 + g + ((j >> 1) * 8);
            if (m < OUTDIM)
                g_fpart[((size_t)ks * 32 + n) * M_FC_PAD + m] = c4[nt][j];
        }
    }
}

// ---------------- spectral crop: FC reduce+bias, DFT, feedback ---------------
__global__ __launch_bounds__(512) void spectral_kernel(
    const float* __restrict__ fc_b, float* __restrict__ outp)
{
    const int b = blockIdx.x;
    __shared__ float a[OUTDIM];
    __shared__ float cre[GRID_N * MODES];
    __shared__ float cim[GRID_N * MODES];

    for (int i = threadIdx.x; i < OUTDIM; i += blockDim.x) {
        float s = fc_b[i];
        #pragma unroll
        for (int ks = 0; ks < KS_FC; ks++)
            s += g_fpart[((size_t)ks * 32 + b) * M_FC_PAD + i];
        a[i] = s;
        outp[b * OUTDIM + i] = s;
    }
    __syncthreads();

    for (int i = threadIdx.x; i < GRID_N * MODES; i += blockDim.x) {
        int m = i / MODES;
        int q = i % MODES;
        float sre = 0.f, sim = 0.f;
        #pragma unroll 5
        for (int n = 0; n < GRID_N; n++) {
            float v = a[m * GRID_N + n];
            sre += v * g_ct[q][n];
            sim -= v * g_st[q][n];
        }
        cre[m * MODES + q] = sre;
        cim[m * MODES + q] = sim;
    }
    __syncthreads();

    for (int i = threadIdx.x; i < MODES * MODES; i += blockDim.x) {
        int p = i / MODES;
        int q = i % MODES;
        float s = 0.f;
        #pragma unroll 5
        for (int m = 0; m < GRID_N; m++)
            s += g_ct[p][m] * cre[m * MODES + q] + g_st[p][m] * cim[m * MODES + q];
        g_x[b][i] = s;
    }
}

// ---------------- driver -----------------------------------------------------
extern "C" void kernel_launch(void* const* d_in, const int* in_sizes, int n_in,
                              void* d_out, int out_size)
{
    const float* x     = (const float*)d_in[0];
    const float* W_ih  = (const float*)d_in[1];
    const float* W_hh  = (const float*)d_in[2];
    const float* b_ih  = (const float*)d_in[3];
    const float* b_hh  = (const float*)d_in[4];
    const float* fc_w  = (const float*)d_in[5];
    const float* fc_b  = (const float*)d_in[6];
    float*       out   = (float*)d_out;

    init_kernel<<<64, 256>>>(x);
    repack_gru<<<592, 256>>>(W_ih, W_hh);
    repack_fc<<<128, 256>>>(fc_w);

    for (int t = 0; t < TIME; t++) {
        int src = t & 1;
        float* outp = out + (size_t)t * BATCH * OUTDIM;

        // K1: ih0 + hh0..2 (hh depend only on old h) — one fat launch
        gru_gemm<<<dim3(48, 8, 4), 128>>>(src, 0, 3, 4, 5);
        gru_cell<<<128, 256>>>(0, src, b_ih, b_hh);
        gru_gemm<<<dim3(48, 8, 1), 128>>>(src, 1, 0, 0, 0);
        gru_cell<<<128, 256>>>(1, src, b_ih, b_hh);
        gru_gemm<<<dim3(48, 8, 1), 128>>>(src, 2, 0, 0, 0);
        gru_cell<<<128, 256>>>(2, src, b_ih, b_hh);
        fc_gemm<<<dim3(40, KS_FC), 128>>>(src);
        spectral_kernel<<<BATCH, 512>>>(fc_b, outp);
    }
}

// round 13
// speedup vs baseline: 1.6041x; 1.0473x over previous
#include <cuda_runtime.h>
#include <cstdint>

#define HID    1024
#define BATCH  32
#define LAYERS 3
#define OUTDIM 2500
#define GRID_N 50
#define MODES  32
#define TIME   64

#define GRU_MT  192         // 3072/16 m-tiles per matrix
#define GRU_KT  128         // 1024/8 k8-tiles
#define KS8     8           // K-slices per matrix (K=128 each)
#define FC_MT   160         // padded 2560/16
#define FC_KT   128
#define KS_FC   16
#define KSLICE_FC 64
#define M_FC_PAD 2512

// ---------------- persistent device state ------------------------------------
__device__ float g_h[2][LAYERS][BATCH][HID];
__device__ float g_x[BATCH][HID];
__device__ float g_ct[MODES][GRID_N];
__device__ float g_st[MODES][GRID_N];
__device__ float g_part6[6 * KS8 * 3072 * 32];        // GRU split-K partials
__device__ float g_fpart[KS_FC * 32 * M_FC_PAD];      // FC partials

// fragment-swizzled fp32 weights: [mat][mt][kt8][128]; mats 0-2 ih, 3-5 hh
__device__ float g_Wsw[(size_t)6 * GRU_MT * GRU_KT * 128];   // 75.5 MB
__device__ float g_Fsw[(size_t)FC_MT * FC_KT * 128];         // 10.5 MB

// ---------------- helpers ----------------------------------------------------
__device__ __forceinline__ uint32_t f2tf(float f) {
    uint32_t u;
    asm("cvt.rna.tf32.f32 %0, %1;" : "=r"(u) : "f"(f));
    return u;
}

__device__ __forceinline__ void mma1688(float* c,
                                        uint32_t a0, uint32_t a1, uint32_t a2, uint32_t a3,
                                        uint32_t b0, uint32_t b1) {
    asm volatile(
        "mma.sync.aligned.m16n8k8.row.col.f32.tf32.tf32.f32 "
        "{%0,%1,%2,%3}, {%4,%5,%6,%7}, {%8,%9}, {%0,%1,%2,%3};"
        : "+f"(c[0]), "+f"(c[1]), "+f"(c[2]), "+f"(c[3])
        : "r"(a0), "r"(a1), "r"(a2), "r"(a3), "r"(b0), "r"(b1));
}

__device__ __forceinline__ uint32_t smem_u32(const void* p) {
    return (uint32_t)__cvta_generic_to_shared(p);
}

__device__ __forceinline__ void cp16(uint32_t dst, const void* src) {
    asm volatile("cp.async.cg.shared.global [%0], [%1], 16;" :: "r"(dst), "l"(src));
}
__device__ __forceinline__ void cp_commit() {
    asm volatile("cp.async.commit_group;");
}
template<int N> __device__ __forceinline__ void cp_wait() {
    asm volatile("cp.async.wait_group %0;" :: "n"(N));
}

// ---------------- init -------------------------------------------------------
__global__ void init_kernel(const float* __restrict__ x)
{
    int tid    = blockIdx.x * blockDim.x + threadIdx.x;
    int stride = gridDim.x * blockDim.x;

    float* hflat = (float*)g_h;
    for (int i = tid; i < 2 * LAYERS * BATCH * HID; i += stride) hflat[i] = 0.0f;

    float* xflat = (float*)g_x;
    for (int i = tid; i < BATCH * HID; i += stride) xflat[i] = x[i];

    for (int i = tid; i < MODES * GRID_N; i += stride) {
        int t = i / GRID_N;
        int n = i % GRID_N;
        float arg = 2.0f * (float)(t - 16) * (float)n / 50.0f;  // units of pi
        g_ct[t][n] = cospif(arg);
        g_st[t][n] = sinpif(arg);
    }
}

// ---------------- weight repack: fp32 fragment order -------------------------
__global__ void repack_gru(const float* __restrict__ W_ih,
                           const float* __restrict__ W_hh)
{
    int64_t total = (int64_t)6 * GRU_MT * GRU_KT * 128;
    for (int64_t idx = (int64_t)blockIdx.x * blockDim.x + threadIdx.x;
         idx < total; idx += (int64_t)gridDim.x * blockDim.x) {
        int within = (int)(idx & 127);
        int e    = within & 3;
        int lane = within >> 2;
        int kt   = (int)((idx >> 7) & (GRU_KT - 1));
        int tmp  = (int)(idx >> 14);           // mat*GRU_MT + mt
        int mt   = tmp % GRU_MT;
        int mat  = tmp / GRU_MT;
        int l    = mat % 3;
        const float* src = ((mat < 3) ? W_ih : W_hh) + (size_t)l * 3 * HID * HID;
        int g = lane >> 2, t = lane & 3;
        int r = mt * 16 + g + (e & 1) * 8;
        int c = kt * 8 + t + (e >> 1) * 4;
        g_Wsw[idx] = src[(size_t)r * HID + c];
    }
}

__global__ void repack_fc(const float* __restrict__ fc_w)
{
    int64_t total = (int64_t)FC_MT * FC_KT * 128;
    for (int64_t idx = (int64_t)blockIdx.x * blockDim.x + threadIdx.x;
         idx < total; idx += (int64_t)gridDim.x * blockDim.x) {
        int within = (int)(idx & 127);
        int e    = within & 3;
        int lane = within >> 2;
        int kt   = (int)((idx >> 7) & (FC_KT - 1));
        int mt   = (int)(idx >> 14);
        int g = lane >> 2, t = lane & 3;
        int r = mt * 16 + g + (e & 1) * 8;
        int c = kt * 8 + t + (e >> 1) * 4;
        g_Fsw[idx] = (r < OUTDIM) ? fc_w[(size_t)r * HID + c] : 0.0f;
    }
}

// ---------------- GRU gate GEMM (split-K, 3xTF32, cp.async, raw-B, PDL) ------
__global__ __launch_bounds__(128, 8) void gru_gemm(
    int src, int j0, int j1, int j2, int j3)
{
    __shared__ float4 sA[2 * 4 * 2 * 32];   // [slot][warp][kt2][lane], 8 KB
    __shared__ float  vB[32 * 132];         // raw fp32 B, stride 132

    cudaGridDependencySynchronize();

    const int mat  = (blockIdx.z == 0) ? j0 : (blockIdx.z == 1) ? j1
                   : (blockIdx.z == 2) ? j2 : j3;
    const int ks   = blockIdx.y;
    const int warp = threadIdx.x >> 5;
    const int lane = threadIdx.x & 31;
    const int g    = lane >> 2;
    const int t    = lane & 3;
    const int m0   = blockIdx.x * 64 + warp * 16;
    const int koff = ks * 128;
    const int l    = mat % 3;

    const int mt = blockIdx.x * 4 + warp;
    const float4* pA4 = (const float4*)(g_Wsw
                      + (((size_t)mat * GRU_MT + mt) * GRU_KT + ks * 16) * 128);
    const uint32_t sA_base = smem_u32(sA);
    const uint32_t vB_base = smem_u32(vB);

    // group 0: B (raw fp32, 16 KB), each thread copies 128 B of one row-quarter
    const float* bsrc = (mat >= 3) ? &g_h[src][l][0][0]
                      : (l == 0)   ? &g_x[0][0]
                                   : &g_h[src ^ 1][l - 1][0][0];
    {
        int n = threadIdx.x >> 2;
        int q = threadIdx.x & 3;
        const float* srcp = bsrc + n * HID + koff + q * 32;
        uint32_t dstp = vB_base + (n * 132 + q * 32) * 4;
        #pragma unroll
        for (int j = 0; j < 8; j++)
            cp16(dstp + j * 16, srcp + j * 4);
        cp_commit();
    }

    auto issue_chunk = [&](int c, int slot) {
        #pragma unroll
        for (int kt = 0; kt < 2; kt++) {
            uint32_t d = sA_base + ((((slot * 4 + warp) * 2 + kt) * 32 + lane) << 4);
            cp16(d, pA4 + (c * 2 + kt) * 32 + lane);
        }
        cp_commit();
    };

    issue_chunk(0, 0);
    issue_chunk(1, 1);

    cp_wait<2>();            // B complete
    __syncthreads();

    float c4[4][4] = {};

    auto process = [&](int c, int slot) {
        #pragma unroll
        for (int kt = 0; kt < 2; kt++) {
            float4 fr = sA[((slot * 4 + warp) * 2 + kt) * 32 + lane];
            int k0 = (c * 2 + kt) * 8;
            uint32_t ah0 = f2tf(fr.x), ah1 = f2tf(fr.y), ah2 = f2tf(fr.z), ah3 = f2tf(fr.w);
            uint32_t al0 = f2tf(fr.x - __uint_as_float(ah0));
            uint32_t al1 = f2tf(fr.y - __uint_as_float(ah1));
            uint32_t al2 = f2tf(fr.z - __uint_as_float(ah2));
            uint32_t al3 = f2tf(fr.w - __uint_as_float(ah3));
            #pragma unroll
            for (int nt = 0; nt < 4; nt++) {
                int n = nt * 8 + g;
                float b0 = vB[n * 132 + k0 + t];
                float b1 = vB[n * 132 + k0 + t + 4];
                uint32_t bh0 = f2tf(b0);
                uint32_t bh1 = f2tf(b1);
                uint32_t bl0 = f2tf(b0 - __uint_as_float(bh0));
                uint32_t bl1 = f2tf(b1 - __uint_as_float(bh1));
                mma1688(c4[nt], ah0, ah1, ah2, ah3, bh0, bh1);
                mma1688(c4[nt], ah0, ah1, ah2, ah3, bl0, bl1);
                mma1688(c4[nt], al0, al1, al2, al3, bh0, bh1);
            }
        }
    };

    // 8 chunks through 2 slots
    cp_wait<1>();  process(0, 0);  issue_chunk(2, 0);
    cp_wait<1>();  process(1, 1);  issue_chunk(3, 1);
    cp_wait<1>();  process(2, 0);  issue_chunk(4, 0);
    cp_wait<1>();  process(3, 1);  issue_chunk(5, 1);
    cp_wait<1>();  process(4, 0);  issue_chunk(6, 0);
    cp_wait<1>();  process(5, 1);  issue_chunk(7, 1);
    cp_wait<1>();  process(6, 0);
    cp_wait<0>();  process(7, 1);

    #pragma unroll
    for (int nt = 0; nt < 4; nt++) {
        int n = nt * 8 + 2 * t;
        float* base = g_part6 + (((size_t)mat * KS8 + ks) * 3072 + (m0 + g)) * 32 + n;
        *(float2*)base            = make_float2(c4[nt][0], c4[nt][1]);
        *(float2*)(base + 8 * 32) = make_float2(c4[nt][2], c4[nt][3]);
    }

    cudaTriggerProgrammaticLaunchCompletion();
}

// ---------------- GRU cell pointwise (PDL) -----------------------------------
__global__ __launch_bounds__(256) void gru_cell(
    int layer, int src,
    const float* __restrict__ b_ih_all,
    const float* __restrict__ b_hh_all)
{
    cudaGridDependencySynchronize();

    const int dst = src ^ 1;
    const int gid = blockIdx.x * 256 + threadIdx.x;
    const int b   = gid & 31;
    const int u   = gid >> 5;

    float i_r = 0.f, i_z = 0.f, i_n = 0.f, h_r = 0.f, h_z = 0.f, h_n = 0.f;
    #pragma unroll
    for (int ks = 0; ks < KS8; ks++) {
        const float* p = g_part6 + ((size_t)layer * KS8 + ks) * 3072 * 32;
        i_r += p[(u)        * 32 + b];
        i_z += p[(u + 1024) * 32 + b];
        i_n += p[(u + 2048) * 32 + b];
    }
    #pragma unroll
    for (int ks = 0; ks < KS8; ks++) {
        const float* p = g_part6 + ((size_t)(3 + layer) * KS8 + ks) * 3072 * 32;
        h_r += p[(u)        * 32 + b];
        h_z += p[(u + 1024) * 32 + b];
        h_n += p[(u + 2048) * 32 + b];
    }

    const float* bih = b_ih_all + layer * 3 * HID;
    const float* bhh = b_hh_all + layer * 3 * HID;
    i_r += bih[u];           h_r += bhh[u];
    i_z += bih[u + HID];     h_z += bhh[u + HID];
    i_n += bih[u + 2 * HID]; h_n += bhh[u + 2 * HID];

    float r = 1.0f / (1.0f + expf(-(i_r + h_r)));
    float z = 1.0f / (1.0f + expf(-(i_z + h_z)));
    float n = tanhf(i_n + r * h_n);

    float h_old = g_h[src][layer][b][u];
    g_h[dst][layer][b][u] = (1.0f - z) * n + z * h_old;

    cudaTriggerProgrammaticLaunchCompletion();
}

// ---------------- FC GEMM (split-K, 3xTF32, cp.async, raw-B, PDL) ------------
__global__ __launch_bounds__(128, 8) void fc_gemm(int src)
{
    __shared__ float4 sA[2 * 4 * 2 * 32];   // 8 KB, 2 ring slots of 2 k8-tiles
    __shared__ float  vB[32 * 76];

    cudaGridDependencySynchronize();

    const int dst  = src ^ 1;
    const int ks   = blockIdx.y;
    const int warp = threadIdx.x >> 5;
    const int lane = threadIdx.x & 31;
    const int g    = lane >> 2;
    const int t    = lane & 3;
    const int m0   = blockIdx.x * 64 + warp * 16;
    const int koff = ks * KSLICE_FC;

    const int mt = blockIdx.x * 4 + warp;
    const float4* pA4 = (const float4*)(g_Fsw
                      + (((size_t)mt) * FC_KT + ks * 8) * 128);
    const uint32_t sA_base = smem_u32(sA);
    const uint32_t vB_base = smem_u32(vB);

    // group 0: B raw fp32 (8 KB)
    const float* bsrc = &g_h[dst][LAYERS - 1][0][0];
    {
        int n = threadIdx.x >> 2;
        int q = threadIdx.x & 3;
        const float* srcp = bsrc + n * HID + koff + q * 16;
        uint32_t dstp = vB_base + (n * 76 + q * 16) * 4;
        #pragma unroll
        for (int j = 0; j < 4; j++)
            cp16(dstp + j * 16, srcp + j * 4);
        cp_commit();
    }

    auto issue_chunk = [&](int c, int slot) {
        #pragma unroll
        for (int kt = 0; kt < 2; kt++) {
            uint32_t d = sA_base + ((((slot * 4 + warp) * 2 + kt) * 32 + lane) << 4);
            cp16(d, pA4 + (c * 2 + kt) * 32 + lane);
        }
        cp_commit();
    };

    issue_chunk(0, 0);
    issue_chunk(1, 1);

    cp_wait<2>();
    __syncthreads();

    float c4[4][4] = {};

    auto process = [&](int c, int slot) {
        #pragma unroll
        for (int kt = 0; kt < 2; kt++) {
            float4 fr = sA[((slot * 4 + warp) * 2 + kt) * 32 + lane];
            int k0 = (c * 2 + kt) * 8;
            uint32_t ah0 = f2tf(fr.x), ah1 = f2tf(fr.y), ah2 = f2tf(fr.z), ah3 = f2tf(fr.w);
            uint32_t al0 = f2tf(fr.x - __uint_as_float(ah0));
            uint32_t al1 = f2tf(fr.y - __uint_as_float(ah1));
            uint32_t al2 = f2tf(fr.z - __uint_as_float(ah2));
            uint32_t al3 = f2tf(fr.w - __uint_as_float(ah3));
            #pragma unroll
            for (int nt = 0; nt < 4; nt++) {
                int n = nt * 8 + g;
                float b0 = vB[n * 76 + k0 + t];
                float b1 = vB[n * 76 + k0 + t + 4];
                uint32_t bh0 = f2tf(b0);
                uint32_t bh1 = f2tf(b1);
                uint32_t bl0 = f2tf(b0 - __uint_as_float(bh0));
                uint32_t bl1 = f2tf(b1 - __uint_as_float(bh1));
                mma1688(c4[nt], ah0, ah1, ah2, ah3, bh0, bh1);
                mma1688(c4[nt], ah0, ah1, ah2, ah3, bl0, bl1);
                mma1688(c4[nt], al0, al1, al2, al3, bh0, bh1);
            }
        }
    };

    cp_wait<1>();  process(0, 0);  issue_chunk(2, 0);
    cp_wait<1>();  process(1, 1);  issue_chunk(3, 1);
    cp_wait<1>();  process(2, 0);
    cp_wait<0>();  process(3, 1);

    #pragma unroll
    for (int nt = 0; nt < 4; nt++) {
        #pragma unroll
        for (int j = 0; j < 4; j++) {
            int n = nt * 8 + 2 * t + (j & 1);
            int m = m0 + g + ((j >> 1) * 8);
            if (m < OUTDIM)
                g_fpart[((size_t)ks * 32 + n) * M_FC_PAD + m] = c4[nt][j];
        }
    }

    cudaTriggerProgrammaticLaunchCompletion();
}

// ---------------- spectral crop: FC reduce+bias, DFT, feedback (PDL) ---------
__global__ __launch_bounds__(512) void spectral_kernel(
    const float* __restrict__ fc_b, float* __restrict__ outp)
{
    const int b = blockIdx.x;
    __shared__ float a[OUTDIM];
    __shared__ float cre[GRID_N * MODES];
    __shared__ float cim[GRID_N * MODES];

    cudaGridDependencySynchronize();

    for (int i = threadIdx.x; i < OUTDIM; i += blockDim.x) {
        float s = fc_b[i];
        #pragma unroll
        for (int ks = 0; ks < KS_FC; ks++)
            s += g_fpart[((size_t)ks * 32 + b) * M_FC_PAD + i];
        a[i] = s;
        outp[b * OUTDIM + i] = s;
    }
    __syncthreads();

    for (int i = threadIdx.x; i < GRID_N * MODES; i += blockDim.x) {
        int m = i / MODES;
        int q = i % MODES;
        float sre = 0.f, sim = 0.f;
        #pragma unroll 5
        for (int n = 0; n < GRID_N; n++) {
            float v = a[m * GRID_N + n];
            sre += v * g_ct[q][n];
            sim -= v * g_st[q][n];
        }
        cre[m * MODES + q] = sre;
        cim[m * MODES + q] = sim;
    }
    __syncthreads();

    for (int i = threadIdx.x; i < MODES * MODES; i += blockDim.x) {
        int p = i / MODES;
        int q = i % MODES;
        float s = 0.f;
        #pragma unroll 5
        for (int m = 0; m < GRID_N; m++)
            s += g_ct[p][m] * cre[m * MODES + q] + g_st[p][m] * cim[m * MODES + q];
        g_x[b][i] = s;
    }

    cudaTriggerProgrammaticLaunchCompletion();
}

// ---------------- driver -----------------------------------------------------
template <typename K, typename... Args>
static inline void launch_pdl(dim3 grid, dim3 block, K kern, Args... args)
{
    cudaLaunchConfig_t cfg = {};
    cfg.gridDim = grid;
    cfg.blockDim = block;
    cfg.dynamicSmemBytes = 0;
    cfg.stream = 0;
    cudaLaunchAttribute attr[1];
    attr[0].id = cudaLaunchAttributeProgrammaticStreamSerialization;
    attr[0].val.programmaticStreamSerializationAllowed = 1;
    cfg.attrs = attr;
    cfg.numAttrs = 1;
    cudaLaunchKernelEx(&cfg, kern, args...);
}

extern "C" void kernel_launch(void* const* d_in, const int* in_sizes, int n_in,
                              void* d_out, int out_size)
{
    const float* x     = (const float*)d_in[0];
    const float* W_ih  = (const float*)d_in[1];
    const float* W_hh  = (const float*)d_in[2];
    const float* b_ih  = (const float*)d_in[3];
    const float* b_hh  = (const float*)d_in[4];
    const float* fc_w  = (const float*)d_in[5];
    const float* fc_b  = (const float*)d_in[6];
    float*       out   = (float*)d_out;

    init_kernel<<<64, 256>>>(x);
    repack_gru<<<592, 256>>>(W_ih, W_hh);
    repack_fc<<<128, 256>>>(fc_w);

    for (int t = 0; t < TIME; t++) {
        int src = t & 1;
        float* outp = out + (size_t)t * BATCH * OUTDIM;

        // K1: ih0 + hh0..2 (hh depend only on old h) — one fat launch
        launch_pdl(dim3(48, 8, 4), dim3(128), gru_gemm, src, 0, 3, 4, 5);
        launch_pdl(dim3(128), dim3(256), gru_cell, 0, src, b_ih, b_hh);
        launch_pdl(dim3(48, 8, 1), dim3(128), gru_gemm, src, 1, 0, 0, 0);
        launch_pdl(dim3(128), dim3(256), gru_cell, 1, src, b_ih, b_hh);
        launch_pdl(dim3(48, 8, 1), dim3(128), gru_gemm, src, 2, 0, 0, 0);
        launch_pdl(dim3(128), dim3(256), gru_cell, 2, src, b_ih, b_hh);
        launch_pdl(dim3(40, KS_FC), dim3(128), fc_gemm, src);
        launch_pdl(dim3(BATCH), dim3(512), spectral_kernel, fc_b, outp);
    }
}